// round 5
// baseline (speedup 1.0000x reference)
#include <cuda_runtime.h>
#include <math.h>

#define Bc 4
#define Nc 1024
#define Hc 8
#define Dc 64
#define BSc 32
#define NBc 32
#define STOP 16
#define SCALE 0.125f

typedef unsigned long long u64;

__device__ float g_kcmp[Bc*NBc*Hc*Dc];
__device__ float g_vcmp[Bc*NBc*Hc*Dc];

__device__ __forceinline__ float siluf(float s) {
    return s / (1.f + __expf(-s));
}
__device__ __forceinline__ u64 ffma2(u64 a, u64 b, u64 c) {
    u64 d;
    asm("fma.rn.f32x2 %0, %1, %2, %3;" : "=l"(d) : "l"(a), "l"(b), "l"(c));
    return d;
}
__device__ __forceinline__ u64 dup2(float x) {
    u64 r;
    asm("mov.b64 %0, {%1, %1};" : "=l"(r) : "f"(x));
    return r;
}
__device__ __forceinline__ float2 u2f2(u64 u) {
    float2 f;
    asm("mov.b64 {%0, %1}, %2;" : "=f"(f.x), "=f"(f.y) : "l"(u));
    return f;
}
__device__ __forceinline__ float f4c(const float4& v, int jj) {
    switch (jj) { case 0: return v.x; case 1: return v.y; case 2: return v.z; default: return v.w; }
}
__device__ __forceinline__ void cpa16(unsigned dst, const void* src) {
    asm volatile("cp.async.cg.shared.global [%0], [%1], 16;" :: "r"(dst), "l"(src) : "memory");
}
#define CP_COMMIT() asm volatile("cp.async.commit_group;" ::: "memory")
#define CP_WAIT(n)  asm volatile("cp.async.wait_group %0;" :: "n"(n) : "memory")

__global__ void meanKV(const float* __restrict__ pk, const float* __restrict__ pv) {
    int blk = blockIdx.x;
    int b  = blk / (NBc*Hc);
    int kb = (blk / Hc) % NBc;
    int h  = blk % Hc;
    int d  = threadIdx.x;
    float sk = 0.f, sv = 0.f;
    int base = ((b*Nc + kb*BSc)*Hc + h)*Dc + d;
    #pragma unroll 8
    for (int j = 0; j < BSc; j++) {
        sk += pk[base + j*Hc*Dc];
        sv += pv[base + j*Hc*Dc];
    }
    int o = ((b*NBc + kb)*Hc + h)*Dc + d;
    g_kcmp[o] = sk * (1.f/BSc);
    g_vcmp[o] = sv * (1.f/BSc);
}

// CTA = (q_block, head, batch); 8 warps; warp w owns rows {w,w+8,w+16,w+24}.
// Phase B: 2-stage cp.async pipeline over single 32-key tiles.
__global__ __launch_bounds__(256, 3) void hstu_main(
    const float* __restrict__ pq, const float* __restrict__ pk,
    const float* __restrict__ pvv, const float* __restrict__ gate_w,
    const int* __restrict__ xoff, float* __restrict__ out)
{
    __shared__ __align__(16) float4 qsh4[32*16];     // 8KB
    __shared__ __align__(16) float4 kbS[2][16*32];   // 2x8KB K swizzled [d4][key^d4]
    __shared__ __align__(16) float4 vbS[2][32*16];   // 2x8KB V [key][d4]
    __shared__ __align__(16) float  p_sh[32*32];     // 4KB
    __shared__ int list[33];
    __shared__ int lcnt;
    __shared__ unsigned unionm;

    int qb = (NBc - 1) - blockIdx.x;   // heavy first
    int h = blockIdx.y, b = blockIdx.z;
    int len = xoff[b+1] - xoff[b];
    if (qb * BSc >= len) return;
    int nvalid = len - qb*BSc; if (nvalid > BSc) nvalid = BSc;
    int t0 = xoff[b];
    int tid = threadIdx.x, lane = tid & 31, w = tid >> 5;

    unsigned qbase = (unsigned)__cvta_generic_to_shared(qsh4);
    unsigned kbase[2], vbase[2];
    kbase[0] = (unsigned)__cvta_generic_to_shared(&kbS[0][0]);
    kbase[1] = (unsigned)__cvta_generic_to_shared(&kbS[1][0]);
    vbase[0] = (unsigned)__cvta_generic_to_shared(&vbS[0][0]);
    vbase[1] = (unsigned)__cvta_generic_to_shared(&vbS[1][0]);

    const ulonglong2* qshU = (const ulonglong2*)qsh4;

    // ---- Phase A staging: q + compressed K/V (one cp.async group) ----
    {
        int r0 = tid >> 4, c4 = tid & 15;
        #pragma unroll
        for (int step = 0; step < 2; step++) {
            int row = r0 + step*16;
            cpa16(qbase + (unsigned)(row*16 + c4)*16u,
                  pq + ((b*Nc + qb*BSc + row)*Hc + h)*Dc + c4*4);
            int gc = ((b*NBc + row)*Hc + h)*Dc + c4*4;
            cpa16(kbase[0] + (unsigned)(c4*32 + (row ^ c4))*16u, g_kcmp + gc);
            cpa16(vbase[0] + (unsigned)(row*16 + c4)*16u,        g_vcmp + gc);
        }
    }
    CP_COMMIT();
    if (tid == 0) unionm = 0;
    CP_WAIT(0);
    __syncthreads();

    u64 accC[4] = {0,0,0,0}, accS[4] = {0,0,0,0};
    unsigned mysel[4];

    // ================= Phase A =================
    {
        const ulonglong2* kbU = (const ulonglong2*)kbS[0];
        const u64*        vbU = (const u64*)vbS[0];
        u64 sa[4] = {0,0,0,0};
        #pragma unroll
        for (int d4 = 0; d4 < 16; d4++) {
            ulonglong2 k0 = kbU[d4*32 + (lane ^ d4)];
            #pragma unroll
            for (int qi = 0; qi < 4; qi++) {
                ulonglong2 q = qshU[(w + qi*8)*16 + d4];
                sa[qi] = ffma2(q.x, k0.x, sa[qi]);
                sa[qi] = ffma2(q.y, k0.y, sa[qi]);
            }
        }
        bool causal = (lane <= qb);
        #pragma unroll
        for (int qi = 0; qi < 4; qi++) {
            int r = w + qi*8;
            float2 fa = u2f2(sa[qi]);
            float sc = (fa.x + fa.y) * SCALE;
            bool rowok = (r < nvalid);
            p_sh[r*32 + lane] = (causal && rowok) ? siluf(sc) : 0.f;

            unsigned sel;
            if (!rowok) {
                sel = 0u;
            } else if (qb < STOP) {
                sel = (1u << (qb + 1)) - 1u;
            } else {
                unsigned ub = __float_as_uint(sc);
                unsigned u = ((int)ub < 0) ? ~ub : (ub | 0x80000000u);
                if (!causal) u = 0u;
                unsigned T = 0u;
                #pragma unroll
                for (int bit = 31; bit >= 0; --bit) {
                    unsigned cand = T | (1u << bit);
                    unsigned bal = __ballot_sync(0xffffffffu, u >= cand);
                    if (__popc(bal) >= STOP) T = cand;
                }
                unsigned gt = __ballot_sync(0xffffffffu, u > T);
                unsigned eq = __ballot_sync(0xffffffffu, u == T);
                int need = STOP - __popc(gt);
                bool take = ((eq >> lane) & 1u) &&
                            (__popc(eq & ((1u << lane) - 1u)) < need);
                unsigned eqt = __ballot_sync(0xffffffffu, take);
                sel = gt | eqt;
            }
            mysel[qi] = sel;
        }
        __syncwarp();
        unsigned wsel0 = mysel[0] | mysel[1] | mysel[2] | mysel[3];
        if (lane == 0) atomicOr(&unionm, wsel0);

        // compressed PV (keys 0..qb)
        int j4hi = qb >> 2;
        for (int j4 = 0; j4 <= j4hi; j4++) {
            float4 pb[4];
            #pragma unroll
            for (int qi = 0; qi < 4; qi++)
                pb[qi] = *(const float4*)&p_sh[(w + qi*8)*32 + j4*4];
            #pragma unroll
            for (int jj = 0; jj < 4; jj++) {
                u64 v = vbU[(j4*4 + jj)*32 + lane];
                #pragma unroll
                for (int qi = 0; qi < 4; qi++)
                    accC[qi] = ffma2(dup2(f4c(pb[qi], jj)), v, accC[qi]);
            }
        }
    }
    unsigned wsel = mysel[0] | mysel[1] | mysel[2] | mysel[3];
    __syncthreads();
    unsigned um = unionm;
    if (tid == 0) {
        int c = 0;
        for (int kb = 0; kb <= qb; kb++)
            if ((um >> kb) & 1u) list[c++] = kb;
        lcnt = c;
    }
    __syncthreads();
    int cnt = lcnt;

    // tile issue: K (swizzled) + V via cp.async, one commit group per tile
    auto issue_tile = [&](int kb, int s) {
        int r0 = tid >> 4, c4 = tid & 15;
        #pragma unroll
        for (int step = 0; step < 2; step++) {
            int row = r0 + step*16;
            int g = ((b*Nc + kb*BSc + row)*Hc + h)*Dc + c4*4;
            cpa16(kbase[s] + (unsigned)(c4*32 + (row ^ c4))*16u, pk + g);
            cpa16(vbase[s] + (unsigned)(row*16 + c4)*16u,        pvv + g);
        }
        CP_COMMIT();
    };

    // ================= Phase B: 2-stage pipeline =================
    if (cnt > 0) issue_tile(list[0], 0);
    if (cnt > 1) issue_tile(list[1], 1);

    for (int it = 0; it < cnt; it++) {
        if (it + 1 < cnt) { CP_WAIT(1); } else { CP_WAIT(0); }
        __syncthreads();
        int kb = list[it];
        int s = it & 1;
        if ((wsel >> kb) & 1u) {
            const ulonglong2* kbU = (const ulonglong2*)kbS[s];
            const u64*        vbU = (const u64*)vbS[s];
            u64 s0[4] = {0,0,0,0};
            #pragma unroll
            for (int d4 = 0; d4 < 16; d4++) {
                ulonglong2 k0 = kbU[d4*32 + (lane ^ d4)];
                #pragma unroll
                for (int qi = 0; qi < 4; qi++) {
                    ulonglong2 q = qshU[(w + qi*8)*16 + d4];
                    s0[qi] = ffma2(q.x, k0.x, s0[qi]);
                    s0[qi] = ffma2(q.y, k0.y, s0[qi]);
                }
            }
            #pragma unroll
            for (int qi = 0; qi < 4; qi++) {
                int r = w + qi*8;
                int jmax = (kb == qb) ? r : 31;
                bool u0 = ((mysel[qi] >> kb) & 1u) && (lane <= jmax);
                float2 f0 = u2f2(s0[qi]);
                p_sh[r*32 + lane] = u0 ? siluf((f0.x + f0.y) * SCALE) : 0.f;
            }
            __syncwarp();
            #pragma unroll
            for (int j4 = 0; j4 < 8; j4++) {
                float4 pb[4];
                #pragma unroll
                for (int qi = 0; qi < 4; qi++)
                    pb[qi] = *(const float4*)&p_sh[(w + qi*8)*32 + j4*4];
                #pragma unroll
                for (int jj = 0; jj < 4; jj++) {
                    u64 v = vbU[(j4*4 + jj)*32 + lane];
                    #pragma unroll
                    for (int qi = 0; qi < 4; qi++)
                        accS[qi] = ffma2(dup2(f4c(pb[qi], jj)), v, accS[qi]);
                }
            }
        }
        __syncthreads();
        if (it + 2 < cnt) issue_tile(list[it + 2], s);
    }

    // ================= Output + gates (epilogue) =================
    const float* qs = (const float*)qsh4;
    const float* gw = gate_w + h*Dc*3;
    #pragma unroll
    for (int qi = 0; qi < 4; qi++) {
        int r = w + qi*8;
        if (r >= nvalid) continue;   // warp-uniform (rows strided by 8)
        float q0 = qs[r*64 + 2*lane], q1 = qs[r*64 + 2*lane + 1];
        float pg0 = q0*gw[(2*lane)*3 + 0] + q1*gw[(2*lane+1)*3 + 0];
        float pg1 = q0*gw[(2*lane)*3 + 1] + q1*gw[(2*lane+1)*3 + 1];
        #pragma unroll
        for (int off = 16; off > 0; off >>= 1) {
            pg0 += __shfl_xor_sync(0xffffffffu, pg0, off);
            pg1 += __shfl_xor_sync(0xffffffffu, pg1, off);
        }
        float gcv = 1.f / (1.f + __expf(-pg0));
        float gsv = 1.f / (1.f + __expf(-pg1));
        float2 c = u2f2(accC[qi]), s2 = u2f2(accS[qi]);
        int n = qb*BSc + r;
        int o = ((t0 + n)*Hc + h)*Dc;
        float2 o2;
        o2.x = c.x*gcv + s2.x*gsv;
        o2.y = c.y*gcv + s2.y*gsv;
        *((float2*)(out + o) + lane) = o2;
    }
}

extern "C" void kernel_launch(void* const* d_in, const int* in_sizes, int n_in,
                              void* d_out, int out_size) {
    const float* pq   = (const float*)d_in[4];
    const float* pk   = (const float*)d_in[5];
    const float* pv   = (const float*)d_in[6];
    const int*   xoff = (const int*)d_in[7];
    const float* gw   = (const float*)d_in[8];
    float* out = (float*)d_out;

    meanKV<<<Bc*NBc*Hc, 64>>>(pk, pv);
    dim3 grid(NBc, Hc, Bc);
    hstu_main<<<grid, 256>>>(pq, pk, pv, gw, xoff, out);
}